// round 4
// baseline (speedup 1.0000x reference)
#include <cuda_runtime.h>
#include <cuda_bf16.h>
#include <cstdint>

// 3x3 cross-correlation, 4096x4096 fp32, pad=1, stride=1.
// out[i][j] = sum_{dr,dc} w[dr*3+dc] * x[i+dr-1][j+dc-1] + bias
//
// Register-rolling, 8 cols per lane, warp strip = 256 wide x 16 rows.
// Direct form: keep 3 shifted input rows (10 floats each) in registers,
// each output row computed once with 9 FMA/output. Interior strips take a
// branch-free loop; image-edge strips take a guarded clone.

#define N_IMG 4096
#define TW    256            // strip width (8 cols x 32 lanes)
#define RPT   16             // output rows per warp
#define WARPS 8
#define TILE_H (RPT * WARPS) // 128 rows per CTA
#define FULLMASK 0xFFFFFFFFu

// v[0..9] = input row values at columns c0-1 .. c0+8
__device__ __forceinline__ void loadrow_fast(const float* __restrict__ rowp,
                                             int c0, int lane, float* v)
{
    const float4 lo = *reinterpret_cast<const float4*>(rowp + c0);
    const float4 hi = *reinterpret_cast<const float4*>(rowp + c0 + 4);
    float lf = __shfl_up_sync(FULLMASK, hi.w, 1);    // lane l-1's col c0+7
    float rt = __shfl_down_sync(FULLMASK, lo.x, 1);  // lane l+1's col c0
    if (lane == 0)  lf = rowp[c0 - 1];
    if (lane == 31) rt = rowp[c0 + 8];
    v[0]=lf;   v[1]=lo.x; v[2]=lo.y; v[3]=lo.z; v[4]=lo.w;
    v[5]=hi.x; v[6]=hi.y; v[7]=hi.z; v[8]=hi.w; v[9]=rt;
}

__device__ __forceinline__ void loadrow_guard(const float* __restrict__ x,
                                              int grow, int c0, int lane,
                                              float* v)
{
    float4 lo = make_float4(0.f,0.f,0.f,0.f);
    float4 hi = make_float4(0.f,0.f,0.f,0.f);
    float le = 0.f, re = 0.f;
    if ((unsigned)grow < (unsigned)N_IMG) {          // warp-uniform
        const float* rowp = x + (size_t)grow * N_IMG;
        lo = *reinterpret_cast<const float4*>(rowp + c0);
        hi = *reinterpret_cast<const float4*>(rowp + c0 + 4);
        if (lane == 0 && c0 > 0)            le = rowp[c0 - 1];
        if (lane == 31 && c0 + 8 < N_IMG)   re = rowp[c0 + 8];
    }
    float lf = __shfl_up_sync(FULLMASK, hi.w, 1);
    float rt = __shfl_down_sync(FULLMASK, lo.x, 1);
    if (lane == 0)  lf = le;
    if (lane == 31) rt = re;
    v[0]=lf;   v[1]=lo.x; v[2]=lo.y; v[3]=lo.z; v[4]=lo.w;
    v[5]=hi.x; v[6]=hi.y; v[7]=hi.z; v[8]=hi.w; v[9]=rt;
}

template<bool GUARD>
__device__ __forceinline__ void do_strip(const float* __restrict__ x,
                                         float* __restrict__ out,
                                         int row0, int tile_x, int lane,
                                         const float* w, float b)
{
    const int c0 = tile_x + lane * 8;
    float r[3][10];

    if (GUARD) {
        loadrow_guard(x, row0 - 1, c0, lane, r[0]);
        loadrow_guard(x, row0,     c0, lane, r[1]);
    } else {
        loadrow_fast(x + (size_t)(row0 - 1) * N_IMG, c0, lane, r[0]);
        loadrow_fast(x + (size_t)row0       * N_IMG, c0, lane, r[1]);
    }

    #pragma unroll
    for (int i = 0; i < RPT; i++) {
        float* r0 = r[ i      % 3];
        float* r1 = r[(i + 1) % 3];
        float* r2 = r[(i + 2) % 3];

        if (GUARD)
            loadrow_guard(x, row0 + i + 1, c0, lane, r2);
        else
            loadrow_fast(x + (size_t)(row0 + i + 1) * N_IMG, c0, lane, r2);

        float o[8];
        #pragma unroll
        for (int j = 0; j < 8; j++) {
            float acc = b;
            acc = fmaf(w[0], r0[j    ], acc);
            acc = fmaf(w[1], r0[j + 1], acc);
            acc = fmaf(w[2], r0[j + 2], acc);
            acc = fmaf(w[3], r1[j    ], acc);
            acc = fmaf(w[4], r1[j + 1], acc);
            acc = fmaf(w[5], r1[j + 2], acc);
            acc = fmaf(w[6], r2[j    ], acc);
            acc = fmaf(w[7], r2[j + 1], acc);
            acc = fmaf(w[8], r2[j + 2], acc);
            o[j] = acc;
        }

        float* orow = out + (size_t)(row0 + i) * N_IMG + c0;
        *reinterpret_cast<float4*>(orow)     = make_float4(o[0], o[1], o[2], o[3]);
        *reinterpret_cast<float4*>(orow + 4) = make_float4(o[4], o[5], o[6], o[7]);
    }
}

__global__ __launch_bounds__(256, 4)
void conv3x3_wide_kernel(const float* __restrict__ x,
                         const float* __restrict__ w9,
                         const float* __restrict__ bias,
                         float* __restrict__ out)
{
    const int lane   = threadIdx.x & 31;
    const int warp   = threadIdx.x >> 5;
    const int tile_x = blockIdx.x * TW;
    const int row0   = blockIdx.y * TILE_H + warp * RPT;

    float w[9];
    #pragma unroll
    for (int i = 0; i < 9; i++) w[i] = __ldg(&w9[i]);
    const float b = __ldg(&bias[0]);

    const bool guard = (row0 == 0) | (row0 + RPT >= N_IMG) |
                       (tile_x == 0) | (tile_x + TW >= N_IMG);

    if (!guard)
        do_strip<false>(x, out, row0, tile_x, lane, w, b);
    else
        do_strip<true >(x, out, row0, tile_x, lane, w, b);
}

extern "C" void kernel_launch(void* const* d_in, const int* in_sizes, int n_in,
                              void* d_out, int out_size)
{
    const float* x    = (const float*)d_in[0];   // 4096*4096
    const float* w9   = (const float*)d_in[1];   // 9
    const float* bias = (const float*)d_in[2];   // 1
    float* out        = (float*)d_out;           // 4096*4096

    dim3 block(256, 1, 1);
    dim3 grid(N_IMG / TW, N_IMG / TILE_H, 1);    // 16 x 32 = 512 CTAs
    conv3x3_wide_kernel<<<grid, block>>>(x, w9, bias, out);
}

// round 5
// speedup vs baseline: 1.0847x; 1.0847x over previous
#include <cuda_runtime.h>
#include <cuda_bf16.h>
#include <cstdint>

// 3x3 cross-correlation, 4096x4096 fp32, pad=1, stride=1.
// out[i][j] = sum_{dr,dc} w[dr*3+dc] * x[i+dr-1][j+dc-1] + bias
//
// Direct-form register pipeline:
//  - warp strip = 256 wide x 16 rows; lane owns 8 consecutive cols.
//  - 3 shifted rows (10 floats) live in registers; 9 FMA per output.
//  - raw prefetch buffer (2 x float4 + edge) for row i+2: LDG issued one
//    full iteration (72 FMAs) before first use -> DRAM latency hidden.
//  - interior strips: branch-free loop; image-edge strips: guarded clone.

#define N_IMG 4096
#define TW    256
#define RPT   16
#define WARPS 8
#define TILE_H (RPT * WARPS)   // 128
#define FULLMASK 0xFFFFFFFFu

struct Raw { float4 lo, hi; float e; };

__device__ __forceinline__ Raw fetch_fast(const float* __restrict__ rowp,
                                          int c0, int lane)
{
    Raw r;
    r.lo = *reinterpret_cast<const float4*>(rowp + c0);
    r.hi = *reinterpret_cast<const float4*>(rowp + c0 + 4);
    r.e  = 0.f;
    if (lane == 0)  r.e = rowp[c0 - 1];
    if (lane == 31) r.e = rowp[c0 + 8];
    return r;
}

__device__ __forceinline__ Raw fetch_guard(const float* __restrict__ x,
                                           int grow, int c0, int lane)
{
    Raw r;
    r.lo = make_float4(0.f,0.f,0.f,0.f);
    r.hi = make_float4(0.f,0.f,0.f,0.f);
    r.e  = 0.f;
    if ((unsigned)grow < (unsigned)N_IMG) {   // warp-uniform
        const float* rowp = x + (size_t)grow * N_IMG;
        r.lo = *reinterpret_cast<const float4*>(rowp + c0);
        r.hi = *reinterpret_cast<const float4*>(rowp + c0 + 4);
        if (lane == 0 && c0 > 0)          r.e = rowp[c0 - 1];
        if (lane == 31 && c0 + 8 < N_IMG) r.e = rowp[c0 + 8];
    }
    return r;
}

// raw -> 10-float shifted row (cols c0-1 .. c0+8)
__device__ __forceinline__ void expand(const Raw& q, int lane, float* v)
{
    float lf = __shfl_up_sync(FULLMASK, q.hi.w, 1);
    float rt = __shfl_down_sync(FULLMASK, q.lo.x, 1);
    if (lane == 0)  lf = q.e;
    if (lane == 31) rt = q.e;
    v[0]=lf;     v[1]=q.lo.x; v[2]=q.lo.y; v[3]=q.lo.z; v[4]=q.lo.w;
    v[5]=q.hi.x; v[6]=q.hi.y; v[7]=q.hi.z; v[8]=q.hi.w; v[9]=rt;
}

template<bool GUARD>
__device__ __forceinline__ void do_strip(const float* __restrict__ x,
                                         float* __restrict__ out,
                                         int row0, int tile_x, int lane,
                                         const float* w, float b)
{
    const int c0 = tile_x + lane * 8;
    float r[3][10];

    // rows row0-1, row0 resident; raw buffer holds row0+1
    Raw pf;
    if (GUARD) {
        Raw a = fetch_guard(x, row0 - 1, c0, lane);
        Raw bq= fetch_guard(x, row0,     c0, lane);
        pf    = fetch_guard(x, row0 + 1, c0, lane);
        expand(a,  lane, r[0]);
        expand(bq, lane, r[1]);
    } else {
        Raw a = fetch_fast(x + (size_t)(row0 - 1) * N_IMG, c0, lane);
        Raw bq= fetch_fast(x + (size_t)row0       * N_IMG, c0, lane);
        pf    = fetch_fast(x + (size_t)(row0 + 1) * N_IMG, c0, lane);
        expand(a,  lane, r[0]);
        expand(bq, lane, r[1]);
    }

    #pragma unroll
    for (int i = 0; i < RPT; i++) {
        // materialize row i+1 from prefetch buffer
        expand(pf, lane, r[(i + 2) % 3]);

        // issue prefetch for row i+2 BEFORE the FMA block (used next iter)
        if (i < RPT - 1) {
            if (GUARD) pf = fetch_guard(x, row0 + i + 2, c0, lane);
            else       pf = fetch_fast (x + (size_t)(row0 + i + 2) * N_IMG, c0, lane);
        }

        const float* r0 = r[ i      % 3];
        const float* r1 = r[(i + 1) % 3];
        const float* r2 = r[(i + 2) % 3];

        float o[8];
        #pragma unroll
        for (int j = 0; j < 8; j++) {
            float acc = b;
            acc = fmaf(w[0], r0[j    ], acc);
            acc = fmaf(w[1], r0[j + 1], acc);
            acc = fmaf(w[2], r0[j + 2], acc);
            acc = fmaf(w[3], r1[j    ], acc);
            acc = fmaf(w[4], r1[j + 1], acc);
            acc = fmaf(w[5], r1[j + 2], acc);
            acc = fmaf(w[6], r2[j    ], acc);
            acc = fmaf(w[7], r2[j + 1], acc);
            acc = fmaf(w[8], r2[j + 2], acc);
            o[j] = acc;
        }

        float* orow = out + (size_t)(row0 + i) * N_IMG + c0;
        *reinterpret_cast<float4*>(orow)     = make_float4(o[0], o[1], o[2], o[3]);
        *reinterpret_cast<float4*>(orow + 4) = make_float4(o[4], o[5], o[6], o[7]);
    }
}

__global__ __launch_bounds__(256, 4)
void conv3x3_pipe_kernel(const float* __restrict__ x,
                         const float* __restrict__ w9,
                         const float* __restrict__ bias,
                         float* __restrict__ out)
{
    const int lane   = threadIdx.x & 31;
    const int warp   = threadIdx.x >> 5;
    const int tile_x = blockIdx.x * TW;
    const int row0   = blockIdx.y * TILE_H + warp * RPT;

    float w[9];
    #pragma unroll
    for (int i = 0; i < 9; i++) w[i] = __ldg(&w9[i]);
    const float b = __ldg(&bias[0]);

    const bool guard = (row0 == 0) | (row0 + RPT >= N_IMG) |
                       (tile_x == 0) | (tile_x + TW >= N_IMG);

    if (!guard)
        do_strip<false>(x, out, row0, tile_x, lane, w, b);
    else
        do_strip<true >(x, out, row0, tile_x, lane, w, b);
}

extern "C" void kernel_launch(void* const* d_in, const int* in_sizes, int n_in,
                              void* d_out, int out_size)
{
    const float* x    = (const float*)d_in[0];   // 4096*4096
    const float* w9   = (const float*)d_in[1];   // 9
    const float* bias = (const float*)d_in[2];   // 1
    float* out        = (float*)d_out;           // 4096*4096

    dim3 block(256, 1, 1);
    dim3 grid(N_IMG / TW, N_IMG / TILE_H, 1);    // 16 x 32 = 512 CTAs
    conv3x3_pipe_kernel<<<grid, block>>>(x, w9, bias, out);
}